// round 16
// baseline (speedup 1.0000x reference)
#include <cuda_runtime.h>
#include <math.h>

#define B 4
#define T 8192
#define C 1024
#define A 1024
#define H 16
#define D 64
#define NC 37              // chunks per batch
#define GRID (B*NC)        // 148 CTAs = one wave
#define SUB 16             // tokens per sub-tile

typedef unsigned long long u64;
typedef unsigned int u32;

// ---------------- scratch (static device globals, no allocation) ----------
__device__ float g_u[B*H*C];           // pre-scaled by 0.125
__device__ float g_state[GRID][2*H];   // [m(16), s(16)] per chunk
__device__ float g_zp[GRID][H][C];     // unnormalized exp-weighted partial z
__device__ float g_z[B*H*C];

// ---------------- bf16x3 split: (x0,x1) -> hi bf16x2, lo bf16x2 ------------
__device__ __forceinline__ void split2(float x0, float x1, u32& hi, u32& lo) {
    u32 h;
    asm("cvt.rn.bf16x2.f32 %0, %1, %2;" : "=r"(h) : "f"(x1), "f"(x0));
    float h0 = __uint_as_float(h << 16);
    float h1 = __uint_as_float(h & 0xffff0000u);
    float l0 = x0 - h0, l1 = x1 - h1;
    u32 l;
    asm("cvt.rn.bf16x2.f32 %0, %1, %2;" : "=r"(l) : "f"(l1), "f"(l0));
    hi = h; lo = l;
}

// ---------------- mma.sync m16n8k16 bf16, D += A*B -------------------------
__device__ __forceinline__ void mma16816(float* d, const u32* a, const u32* bb) {
    asm volatile(
        "mma.sync.aligned.m16n8k16.row.col.f32.bf16.bf16.f32 "
        "{%0,%1,%2,%3}, {%4,%5,%6,%7}, {%8,%9}, {%0,%1,%2,%3};"
        : "+f"(d[0]), "+f"(d[1]), "+f"(d[2]), "+f"(d[3])
        : "r"(a[0]), "r"(a[1]), "r"(a[2]), "r"(a[3]), "r"(bb[0]), "r"(bb[1]));
}

// ---------------- ldmatrix wrappers ----------------------------------------
__device__ __forceinline__ void ldsm_x4(u32* r, u32 addr) {
    asm volatile("ldmatrix.sync.aligned.m8n8.x4.shared.b16 {%0,%1,%2,%3}, [%4];"
        : "=r"(r[0]), "=r"(r[1]), "=r"(r[2]), "=r"(r[3]) : "r"(addr));
}
__device__ __forceinline__ void ldsm_x2t(u32* r, u32 addr) {
    asm volatile("ldmatrix.sync.aligned.m8n8.x2.trans.shared.b16 {%0,%1}, [%2];"
        : "=r"(r[0]), "=r"(r[1]) : "r"(addr));
}

// ---------------------------------------------------------------------------
// K0 (fused q+u): one CTA per (b,h).
//   Phase 1: 8 warps compute the 64 q values of head h (warp w: d = w*8..w*8+7)
//   Phase 2: u[b,h,col] = 0.125 * sum_d q[d] * Wk[h*64+d, col]
// bk dropped: per-(b,h) constant cancels in softmax.
// ---------------------------------------------------------------------------
__global__ void qu_kernel(const float* __restrict__ x,
                          const float* __restrict__ Wq,
                          const float* __restrict__ bq,
                          const float* __restrict__ Wk) {
    int b = blockIdx.x >> 4, h = blockIdx.x & 15;
    __shared__ float qs[D];
    int warp = threadIdx.x >> 5, lane = threadIdx.x & 31;
    const float4* xr = (const float4*)(x + ((size_t)b * T + (T - 1)) * C);

    #pragma unroll
    for (int dd = 0; dd < 8; dd++) {
        int d = warp * 8 + dd;
        const float4* wr = (const float4*)(Wq + (size_t)(h * D + d) * C);
        float s = 0.f;
        #pragma unroll 4
        for (int c = lane; c < C / 4; c += 32) {
            float4 w = wr[c], xv = xr[c];
            s += w.x * xv.x + w.y * xv.y + w.z * xv.z + w.w * xv.w;
        }
        #pragma unroll
        for (int o = 16; o; o >>= 1) s += __shfl_down_sync(0xffffffffu, s, o);
        if (!lane) qs[d] = s + bq[h * D + d];
    }
    __syncthreads();

    for (int cc = threadIdx.x; cc < C; cc += 256) {
        float acc = 0.f;
        #pragma unroll 16
        for (int d = 0; d < D; d++)
            acc += qs[d] * Wk[(size_t)(h * D + d) * C + cc];
        g_u[(b * H + h) * C + cc] = acc * 0.125f;
    }
}

// ---------------------------------------------------------------------------
// K1 (fused main): single pass over x, 256 threads / 8 warps.
// WARP-LOCAL pipeline: each warp loads/converts/consumes its own 128-col
// slice (cp.async + split + ldmatrix + both mmas all warp-private).
// Only the softmax combine/broadcast uses CTA barriers (2 per sub-tile).
// ---------------------------------------------------------------------------
struct __align__(16) FSmem {
    float xs[SUB * 1024];       // 65536 B single f32 tile (warp-sliced)
    u32   xh[SUB * 512];        // 32768 B bf16-hi: warp*4096 + row*256 bytes
    u32   xl[SUB * 512];        // 32768 B bf16-lo
    float spart[8][SUB][18];    // per-warp score partials (padded)
    float wts[H][SUB];          // exp weights (f32)
    float rfac[H];
    float mrun[H];
    float srun[H];
    int   norescale;            // 1 if all rfac == 1.0 this sub-tile
};

__device__ __forceinline__ void cp16(float* d, const float* s) {
    unsigned a = (unsigned)__cvta_generic_to_shared(d);
    asm volatile("cp.async.cg.shared.global [%0], [%1], 16;" :: "r"(a), "l"(s) : "memory");
}

__global__ __launch_bounds__(256, 1)
void fused_kernel(const float* __restrict__ x) {
    extern __shared__ char smraw[];
    FSmem& sm = *reinterpret_cast<FSmem*>(smraw);

    int tid = threadIdx.x;
    int lane = tid & 31, warp = tid >> 5;
    int blk = blockIdx.x;
    int b = blk / NC, c = blk % NC;
    int t0 = (c * T) / NC, t1 = ((c + 1) * T) / NC;
    int len = t1 - t0;
    int nsub = (len + SUB - 1) / SUB;

    u32 xh_b = (u32)__cvta_generic_to_shared(sm.xh) + warp * 4096;
    u32 xl_b = (u32)__cvta_generic_to_shared(sm.xl) + warp * 4096;

    // ---- load this warp's u B-fragments into registers (hi/lo split) ----
    u32 ubh[8][2][2], ubl[8][2][2];
    {
        int hq = lane >> 2, cc2i = (lane & 3) * 2;
        #pragma unroll
        for (int kk = 0; kk < 8; kk++)
            #pragma unroll
            for (int nt = 0; nt < 2; nt++) {
                const float* up = g_u + ((size_t)(b * H) + nt * 8 + hq) * C
                                  + warp * 128 + kk * 16 + cc2i;
                float2 p0 = *(const float2*)(up);
                float2 p1 = *(const float2*)(up + 8);
                split2(p0.x, p0.y, ubh[kk][nt][0], ubl[kk][nt][0]);
                split2(p1.x, p1.y, ubh[kk][nt][1], ubl[kk][nt][1]);
            }
    }

    if (tid < H) { sm.mrun[tid] = -1e30f; sm.srun[tid] = 0.f; }
    __syncthreads();    // mrun/srun init visible before first softmax

    // warp-slice base pointers (f32 tile): row j at j*1024 + warp*128 + lane*4
    float* fs = sm.xs + warp * 128 + lane * 4;
    const float* xg = x + ((size_t)b * T + t0) * C + warp * 128 + lane * 4;

    // z accumulators: 16 n-tiles x 4 fp32 D-fragment regs (rows = heads)
    float zd[16][4];
    #pragma unroll
    for (int nt = 0; nt < 16; nt++)
        #pragma unroll
        for (int j = 0; j < 4; j++) zd[nt][j] = 0.f;

    // prefetch tile 0 (len >= 221 > SUB: all rows valid)
    #pragma unroll
    for (int j = 0; j < SUB; j++)
        cp16(fs + j * 1024, xg + (size_t)j * C);
    asm volatile("cp.async.commit_group;" ::: "memory");

    int r   = lane >> 2;         // fragment row
    int cc2 = (lane & 3) * 2;    // fragment col pair

    // ldmatrix row bases (warp-local slices, 256B row pitch)
    int rowA = lane & 15;
    int hi8  = lane >> 4;
    u32 aRowH = xh_b + rowA * 256;
    u32 aRowL = xl_b + rowA * 256;
    int swA = rowA & 7;
    int tB  = lane & 15;
    u32 bRowH = xh_b + tB * 256;
    u32 bRowL = xl_b + tB * 256;
    int swB = tB & 7;

    for (int k = 0; k < nsub; k++) {
        asm volatile("cp.async.wait_group 0;" ::: "memory");
        __syncwarp();   // z(k-1) ldmatrix reads done before bf16 overwrite

        if (tid == 0) sm.norescale = 1;

        // ---- convert own slice: f32 -> swizzled bf16 hi/lo (warp-local) ----
        {
            char* hrow = (char*)sm.xh + warp * 4096;
            char* lrow = (char*)sm.xl + warp * 4096;
            u32 offbase = ((u32)(lane & 1)) << 3;
            #pragma unroll
            for (int j = 0; j < SUB; j++) {
                float4 v = *(const float4*)(fs + j * 1024);
                u32 h0, l0, h1, l1;
                split2(v.x, v.y, h0, l0);
                split2(v.z, v.w, h1, l1);
                u32 off = ((((u32)(lane >> 1)) ^ (u32)(j & 7)) << 4) | offbase;
                *(uint2*)(hrow + j * 256 + off) = make_uint2(h0, h1);
                *(uint2*)(lrow + j * 256 + off) = make_uint2(l0, l1);
            }
        }

        // ---- prefetch k+1 into the (now free) f32 slice (warp-local) ----
        if (k + 1 < nsub) {
            const float* g = xg + (size_t)(k + 1) * SUB * C;
            int rem = len - (k + 1) * SUB;
            #pragma unroll
            for (int j = 0; j < SUB; j++) {
                if (j < rem) cp16(fs + j * 1024, g + (size_t)j * C);
                else *(float4*)(fs + j * 1024) = make_float4(0.f, 0.f, 0.f, 0.f);
            }
        }
        asm volatile("cp.async.commit_group;" ::: "memory");
        __syncwarp();   // bf16 slice visible across the warp

        // ---- scores via tensor cores (warp-local A-frags, u B-frags) ----
        {
            float a0[4] = {0.f,0.f,0.f,0.f}, b0[4] = {0.f,0.f,0.f,0.f}, c0[4] = {0.f,0.f,0.f,0.f};
            float a1[4] = {0.f,0.f,0.f,0.f}, b1[4] = {0.f,0.f,0.f,0.f}, c1[4] = {0.f,0.f,0.f,0.f};
            #pragma unroll
            for (int kk = 0; kk < 8; kk++) {
                u32 chunk = (u32)(((kk << 1) + hi8) ^ swA);
                u32 ah[4], al[4];
                ldsm_x4(ah, aRowH + (chunk << 4));
                ldsm_x4(al, aRowL + (chunk << 4));
                mma16816(a0, ah, ubh[kk][0]);
                mma16816(b0, al, ubh[kk][0]);
                mma16816(c0, ah, ubl[kk][0]);
                mma16816(a1, ah, ubh[kk][1]);
                mma16816(b1, al, ubh[kk][1]);
                mma16816(c1, ah, ubl[kk][1]);
            }
            *(float2*)&sm.spart[warp][r][cc2] =
                make_float2(a0[0] + b0[0] + c0[0], a0[1] + b0[1] + c0[1]);
            *(float2*)&sm.spart[warp][r + 8][cc2] =
                make_float2(a0[2] + b0[2] + c0[2], a0[3] + b0[3] + c0[3]);
            *(float2*)&sm.spart[warp][r][8 + cc2] =
                make_float2(a1[0] + b1[0] + c1[0], a1[1] + b1[1] + c1[1]);
            *(float2*)&sm.spart[warp][r + 8][8 + cc2] =
                make_float2(a1[2] + b1[2] + c1[2], a1[3] + b1[3] + c1[3]);
        }
        __syncthreads();   // (C) spart complete across warps

        // ---- combine partials + online softmax (warp w: heads 2w, 2w+1) ----
        {
            int hh = 2 * warp + (lane >> 4);
            int t = lane & 15;
            int vtok = len - k * SUB; if (vtok > SUB) vtok = SUB;
            float s = 0.f;
            #pragma unroll
            for (int w = 0; w < 8; w++) s += sm.spart[w][t][hh];
            float mloc = (t < vtok) ? s : -1e30f;
            #pragma unroll
            for (int o = 1; o < 16; o <<= 1)
                mloc = fmaxf(mloc, __shfl_xor_sync(0xffffffffu, mloc, o));
            float mold = sm.mrun[hh];
            float mnew = fmaxf(mold, mloc);
            float wgt = (t < vtok) ? __expf(s - mnew) : 0.f;
            sm.wts[hh][t] = wgt;
            float ssum = wgt;
            #pragma unroll
            for (int o = 1; o < 16; o <<= 1)
                ssum += __shfl_xor_sync(0xffffffffu, ssum, o);
            if (t == 0) {
                float rr = __expf(mold - mnew);
                sm.rfac[hh] = rr;
                sm.mrun[hh] = mnew;
                sm.srun[hh] = sm.srun[hh] * rr + ssum;
                if (rr != 1.0f) sm.norescale = 0;
            }
        }
        __syncthreads();   // (D) weights + flag ready

        // ---- z via tensor cores: Z[16h x 128c] += W[16h x 16t] . X[16t x 128c]
        {
            u32 wah[4], wal[4];
            split2(sm.wts[r][cc2],     sm.wts[r][cc2 + 1],     wah[0], wal[0]);
            split2(sm.wts[r + 8][cc2], sm.wts[r + 8][cc2 + 1], wah[1], wal[1]);
            split2(sm.wts[r][cc2 + 8],     sm.wts[r][cc2 + 9],     wah[2], wal[2]);
            split2(sm.wts[r + 8][cc2 + 8], sm.wts[r + 8][cc2 + 9], wah[3], wal[3]);

            if (!sm.norescale) {          // block-uniform branch; exact skip
                float rf0 = sm.rfac[r], rf1 = sm.rfac[r + 8];
                #pragma unroll
                for (int nt = 0; nt < 16; nt++) {
                    zd[nt][0] *= rf0; zd[nt][1] *= rf0;
                    zd[nt][2] *= rf1; zd[nt][3] *= rf1;
                }
            }

            #pragma unroll
            for (int nt = 0; nt < 16; nt++) {
                u32 chunk = (u32)(nt ^ swB);
                u32 bh[2], bl[2];
                ldsm_x2t(bh, bRowH + (chunk << 4));
                ldsm_x2t(bl, bRowL + (chunk << 4));
                float* d = zd[nt];
                mma16816(d, wah, bh);   // Whi * Xhi
                mma16816(d, wal, bh);   // Wlo * Xhi
                mma16816(d, wah, bl);   // Whi * Xlo
            }
        }
        // next iteration's top __syncwarp orders z reads vs bf16 overwrite
    }

    // ---- epilogue: write chunk state + partial z (D rows = heads) ----
    if (tid < H) {
        g_state[blk][tid] = sm.mrun[tid];
        g_state[blk][H + tid] = sm.srun[tid];
    }
    #pragma unroll
    for (int nt = 0; nt < 16; nt++) {
        int col = warp * 128 + nt * 8 + cc2;
        *(float2*)&g_zp[blk][r][col]     = make_float2(zd[nt][0], zd[nt][1]);
        *(float2*)&g_zp[blk][r + 8][col] = make_float2(zd[nt][2], zd[nt][3]);
    }
}

// ---------------------------------------------------------------------------
// K2: combine chunk partials -> normalized z[b,h,:]
// Loads issue FIRST; softmax factors computed redundantly per warp.
// ---------------------------------------------------------------------------
__global__ void combine_kernel() {
    int bh = blockIdx.x >> 4;
    int seg = blockIdx.x & 15;
    int b = bh >> 4, h = bh & 15;
    __shared__ float4 part[128];
    int tid = threadIdx.x;
    int lane = tid & 31;

    int col = seg * 16 + (tid & 15);     // float4 column 0..255
    int strip = tid >> 4;                // 0..7, 5 chunks each (padded to 40)
    int cbase = strip * 5;

    float4 v[5];
    #pragma unroll
    for (int i = 0; i < 5; i++) {
        int cc = cbase + i;
        v[i] = (cc < NC) ? ((const float4*)g_zp[b * NC + cc][h])[col]
                         : make_float4(0.f, 0.f, 0.f, 0.f);
    }

    float m0 = g_state[b * NC + lane][h];
    float m1 = (lane + 32 < NC) ? g_state[b * NC + lane + 32][h] : -1e30f;
    float s0 = g_state[b * NC + lane][H + h];
    float s1 = (lane + 32 < NC) ? g_state[b * NC + lane + 32][H + h] : 0.f;
    float mg = fmaxf(m0, m1);
    #pragma unroll
    for (int o = 16; o; o >>= 1)
        mg = fmaxf(mg, __shfl_xor_sync(0xffffffffu, mg, o));
    float f0 = __expf(m0 - mg), f1 = __expf(m1 - mg);
    float S = f0 * s0 + f1 * s1;
    #pragma unroll
    for (int o = 16; o; o >>= 1)
        S += __shfl_xor_sync(0xffffffffu, S, o);
    float inv = 1.f / S;

    float4 acc = make_float4(0.f, 0.f, 0.f, 0.f);
    #pragma unroll
    for (int i = 0; i < 5; i++) {
        int cc = cbase + i;
        float flo = __shfl_sync(0xffffffffu, f0, cc & 31);
        float fhi = __shfl_sync(0xffffffffu, f1, (cc - 32) & 31);
        float fv = (cc < 32) ? flo : fhi;
        acc.x += fv * v[i].x; acc.y += fv * v[i].y;
        acc.z += fv * v[i].z; acc.w += fv * v[i].w;
    }
    part[tid] = acc;
    __syncthreads();
    if (strip == 0) {
        float4 z = part[tid];
        #pragma unroll
        for (int s = 1; s < 8; s++) {
            float4 p = part[tid + 16 * s];
            z.x += p.x; z.y += p.y; z.z += p.z; z.w += p.w;
        }
        ((float4*)(g_z + (size_t)(b * H + h) * C))[col] =
            make_float4(z.x * inv, z.y * inv, z.z * inv, z.w * inv);
    }
}

// ---------------------------------------------------------------------------
// K3: y[b,a] = Wv[a,:] . z[b, a/64, :] + bv[a]   (warp per (b,a); grid 512)
// ---------------------------------------------------------------------------
__global__ void y_kernel(const float* __restrict__ Wv,
                         const float* __restrict__ bv,
                         float* __restrict__ out) {
    int gw = blockIdx.x * 8 + (threadIdx.x >> 5);
    int lane = threadIdx.x & 31;
    int b = gw >> 10, a = gw & 1023;
    int h = a >> 6;
    const float4* wr = (const float4*)(Wv + (size_t)a * C);
    const float4* zr = (const float4*)(g_z + (size_t)(b * H + h) * C);
    float s = 0.f;
    #pragma unroll 8
    for (int c = lane; c < C / 4; c += 32) {
        float4 w = wr[c], zv = zr[c];
        s += w.x * zv.x + w.y * zv.y + w.z * zv.z + w.w * zv.w;
    }
    #pragma unroll
    for (int o = 16; o; o >>= 1) s += __shfl_down_sync(0xffffffffu, s, o);
    if (!lane) out[b * A + a] = s + bv[a];
}

// ---------------------------------------------------------------------------
extern "C" void kernel_launch(void* const* d_in, const int* in_sizes, int n_in,
                              void* d_out, int out_size) {
    const float* x  = (const float*)d_in[0];
    const float* Wk = (const float*)d_in[1];
    // d_in[2] = bk: per-(b,h) constant, cancels in softmax
    const float* Wq = (const float*)d_in[3];
    const float* bq = (const float*)d_in[4];
    const float* Wv = (const float*)d_in[5];
    const float* bv = (const float*)d_in[6];
    float* out = (float*)d_out;

    cudaFuncSetAttribute(fused_kernel,
                         cudaFuncAttributeMaxDynamicSharedMemorySize,
                         (int)sizeof(FSmem));

    qu_kernel<<<B * H, 256>>>(x, Wq, bq, Wk);
    fused_kernel<<<GRID, 256, sizeof(FSmem)>>>(x);
    combine_kernel<<<B * H * 16, 128>>>();
    y_kernel<<<(B * A) / 8, 256>>>(Wv, bv, out);
}

// round 17
// speedup vs baseline: 1.0861x; 1.0861x over previous
#include <cuda_runtime.h>
#include <math.h>

#define B 4
#define T 8192
#define C 1024
#define A 1024
#define H 16
#define D 64
#define NC 37              // chunks per batch
#define GRID (B*NC)        // 148 CTAs = one wave
#define SUB 16             // tokens per sub-tile

typedef unsigned long long u64;
typedef unsigned int u32;

// ---------------- scratch (static device globals, no allocation) ----------
__device__ float g_q[B*A];
__device__ float g_u[B*H*C];           // pre-scaled by 0.125
__device__ float g_state[GRID][2*H];   // [m(16), s(16)] per chunk
__device__ float g_zp[GRID][H][C];     // unnormalized exp-weighted partial z
__device__ float g_z[B*H*C];

// ---------------- bf16x3 split: (x0,x1) -> hi bf16x2, lo bf16x2 ------------
__device__ __forceinline__ void split2(float x0, float x1, u32& hi, u32& lo) {
    u32 h;
    asm("cvt.rn.bf16x2.f32 %0, %1, %2;" : "=r"(h) : "f"(x1), "f"(x0));
    float h0 = __uint_as_float(h << 16);
    float h1 = __uint_as_float(h & 0xffff0000u);
    float l0 = x0 - h0, l1 = x1 - h1;
    u32 l;
    asm("cvt.rn.bf16x2.f32 %0, %1, %2;" : "=r"(l) : "f"(l1), "f"(l0));
    hi = h; lo = l;
}

// ---------------- mma.sync m16n8k16 bf16, D += A*B -------------------------
__device__ __forceinline__ void mma16816(float* d, const u32* a, const u32* bb) {
    asm volatile(
        "mma.sync.aligned.m16n8k16.row.col.f32.bf16.bf16.f32 "
        "{%0,%1,%2,%3}, {%4,%5,%6,%7}, {%8,%9}, {%0,%1,%2,%3};"
        : "+f"(d[0]), "+f"(d[1]), "+f"(d[2]), "+f"(d[3])
        : "r"(a[0]), "r"(a[1]), "r"(a[2]), "r"(a[3]), "r"(bb[0]), "r"(bb[1]));
}

// ---------------- ldmatrix wrappers ----------------------------------------
__device__ __forceinline__ void ldsm_x4(u32* r, u32 addr) {
    asm volatile("ldmatrix.sync.aligned.m8n8.x4.shared.b16 {%0,%1,%2,%3}, [%4];"
        : "=r"(r[0]), "=r"(r[1]), "=r"(r[2]), "=r"(r[3]) : "r"(addr));
}
__device__ __forceinline__ void ldsm_x2t(u32* r, u32 addr) {
    asm volatile("ldmatrix.sync.aligned.m8n8.x2.trans.shared.b16 {%0,%1}, [%2];"
        : "=r"(r[0]), "=r"(r[1]) : "r"(addr));
}

// ---------------------------------------------------------------------------
// K0: q[b,a] = Wq[a,:] . x[b,T-1,:] + bq[a]    (warp per (b,a); grid 512)
// ---------------------------------------------------------------------------
__global__ void q_kernel(const float* __restrict__ x,
                         const float* __restrict__ Wq,
                         const float* __restrict__ bq) {
    int gw = blockIdx.x * 8 + (threadIdx.x >> 5);
    int lane = threadIdx.x & 31;
    int b = gw >> 10, a = gw & 1023;
    const float4* xr = (const float4*)(x + ((size_t)b * T + (T - 1)) * C);
    const float4* wr = (const float4*)(Wq + (size_t)a * C);
    float s = 0.f;
    #pragma unroll 8
    for (int c = lane; c < C / 4; c += 32) {
        float4 w = wr[c], xv = xr[c];
        s += w.x * xv.x + w.y * xv.y + w.z * xv.z + w.w * xv.w;
    }
    #pragma unroll
    for (int o = 16; o; o >>= 1) s += __shfl_down_sync(0xffffffffu, s, o);
    if (!lane) g_q[b * A + a] = s + bq[a];
}

// ---------------------------------------------------------------------------
// K1: u[b,h,col] = 0.125 * sum_d q[b,h,d] * Wk[h*64+d, col]
// ---------------------------------------------------------------------------
__global__ void u_kernel(const float* __restrict__ Wk) {
    int h = blockIdx.x >> 3, cs = blockIdx.x & 7;
    __shared__ float qs[B][D];
    int tid = threadIdx.x;   // 128 threads
    #pragma unroll
    for (int i = tid; i < B * D; i += 128) {
        int b = i >> 6, d = i & 63;
        qs[b][d] = g_q[b * A + h * D + d];
    }
    __syncthreads();
    int col = cs * 128 + tid;
    float a0 = 0.f, a1 = 0.f, a2 = 0.f, a3 = 0.f;
    const float* wp = Wk + (size_t)(h * D) * C + col;
    #pragma unroll 8
    for (int d = 0; d < D; d++) {
        float w = wp[(size_t)d * C];
        a0 += qs[0][d] * w;
        a1 += qs[1][d] * w;
        a2 += qs[2][d] * w;
        a3 += qs[3][d] * w;
    }
    g_u[(0 * H + h) * C + col] = a0 * 0.125f;
    g_u[(1 * H + h) * C + col] = a1 * 0.125f;
    g_u[(2 * H + h) * C + col] = a2 * 0.125f;
    g_u[(3 * H + h) * C + col] = a3 * 0.125f;
}

// ---------------------------------------------------------------------------
// K2 (fused main): single pass over x, 256 threads / 8 warps. (R14 config)
// WARP-LOCAL pipeline: each warp loads/converts/consumes its own 128-col
// slice. Only the softmax combine/broadcast uses CTA barriers (2/sub-tile).
// ---------------------------------------------------------------------------
struct __align__(16) FSmem {
    float xs[SUB * 1024];       // 65536 B single f32 tile (warp-sliced)
    u32   xh[SUB * 512];        // 32768 B bf16-hi: warp*4096 + row*256 bytes
    u32   xl[SUB * 512];        // 32768 B bf16-lo
    float spart[8][SUB][18];    // per-warp score partials (padded)
    float wts[H][SUB];          // exp weights (f32)
    float rfac[H];
    float mrun[H];
    float srun[H];
    int   norescale;            // 1 if all rfac == 1.0 this sub-tile
};

__device__ __forceinline__ void cp16(float* d, const float* s) {
    unsigned a = (unsigned)__cvta_generic_to_shared(d);
    asm volatile("cp.async.cg.shared.global [%0], [%1], 16;" :: "r"(a), "l"(s) : "memory");
}

__global__ __launch_bounds__(256, 1)
void fused_kernel(const float* __restrict__ x) {
    extern __shared__ char smraw[];
    FSmem& sm = *reinterpret_cast<FSmem*>(smraw);

    int tid = threadIdx.x;
    int lane = tid & 31, warp = tid >> 5;
    int blk = blockIdx.x;
    int b = blk / NC, c = blk % NC;
    int t0 = (c * T) / NC, t1 = ((c + 1) * T) / NC;
    int len = t1 - t0;
    int nsub = (len + SUB - 1) / SUB;

    u32 xh_b = (u32)__cvta_generic_to_shared(sm.xh) + warp * 4096;
    u32 xl_b = (u32)__cvta_generic_to_shared(sm.xl) + warp * 4096;

    // ---- load this warp's u B-fragments into registers (hi/lo split) ----
    u32 ubh[8][2][2], ubl[8][2][2];
    {
        int hq = lane >> 2, cc2i = (lane & 3) * 2;
        #pragma unroll
        for (int kk = 0; kk < 8; kk++)
            #pragma unroll
            for (int nt = 0; nt < 2; nt++) {
                const float* up = g_u + ((size_t)(b * H) + nt * 8 + hq) * C
                                  + warp * 128 + kk * 16 + cc2i;
                float2 p0 = *(const float2*)(up);
                float2 p1 = *(const float2*)(up + 8);
                split2(p0.x, p0.y, ubh[kk][nt][0], ubl[kk][nt][0]);
                split2(p1.x, p1.y, ubh[kk][nt][1], ubl[kk][nt][1]);
            }
    }

    if (tid < H) { sm.mrun[tid] = -1e30f; sm.srun[tid] = 0.f; }
    __syncthreads();    // mrun/srun init visible before first softmax

    // warp-slice base pointers (f32 tile): row j at j*1024 + warp*128 + lane*4
    float* fs = sm.xs + warp * 128 + lane * 4;
    const float* xg = x + ((size_t)b * T + t0) * C + warp * 128 + lane * 4;

    // z accumulators: 16 n-tiles x 4 fp32 D-fragment regs (rows = heads)
    float zd[16][4];
    #pragma unroll
    for (int nt = 0; nt < 16; nt++)
        #pragma unroll
        for (int j = 0; j < 4; j++) zd[nt][j] = 0.f;

    // prefetch tile 0 (len >= 221 > SUB: all rows valid)
    #pragma unroll
    for (int j = 0; j < SUB; j++)
        cp16(fs + j * 1024, xg + (size_t)j * C);
    asm volatile("cp.async.commit_group;" ::: "memory");

    int r   = lane >> 2;         // fragment row
    int cc2 = (lane & 3) * 2;    // fragment col pair

    // ldmatrix row bases (warp-local slices, 256B row pitch)
    int rowA = lane & 15;
    int hi8  = lane >> 4;
    u32 aRowH = xh_b + rowA * 256;
    u32 aRowL = xl_b + rowA * 256;
    int swA = rowA & 7;
    int tB  = lane & 15;
    u32 bRowH = xh_b + tB * 256;
    u32 bRowL = xl_b + tB * 256;
    int swB = tB & 7;

    for (int k = 0; k < nsub; k++) {
        asm volatile("cp.async.wait_group 0;" ::: "memory");
        __syncwarp();   // z(k-1) ldmatrix reads done before bf16 overwrite

        if (tid == 0) sm.norescale = 1;

        // ---- convert own slice: f32 -> swizzled bf16 hi/lo (warp-local) ----
        {
            char* hrow = (char*)sm.xh + warp * 4096;
            char* lrow = (char*)sm.xl + warp * 4096;
            u32 offbase = ((u32)(lane & 1)) << 3;
            #pragma unroll
            for (int j = 0; j < SUB; j++) {
                float4 v = *(const float4*)(fs + j * 1024);
                u32 h0, l0, h1, l1;
                split2(v.x, v.y, h0, l0);
                split2(v.z, v.w, h1, l1);
                u32 off = ((((u32)(lane >> 1)) ^ (u32)(j & 7)) << 4) | offbase;
                *(uint2*)(hrow + j * 256 + off) = make_uint2(h0, h1);
                *(uint2*)(lrow + j * 256 + off) = make_uint2(l0, l1);
            }
        }

        // ---- prefetch k+1 into the (now free) f32 slice (warp-local) ----
        if (k + 1 < nsub) {
            const float* g = xg + (size_t)(k + 1) * SUB * C;
            int rem = len - (k + 1) * SUB;
            #pragma unroll
            for (int j = 0; j < SUB; j++) {
                if (j < rem) cp16(fs + j * 1024, g + (size_t)j * C);
                else *(float4*)(fs + j * 1024) = make_float4(0.f, 0.f, 0.f, 0.f);
            }
        }
        asm volatile("cp.async.commit_group;" ::: "memory");
        __syncwarp();   // bf16 slice visible across the warp

        // ---- scores via tensor cores (warp-local A-frags, u B-frags) ----
        {
            float a0[4] = {0.f,0.f,0.f,0.f}, b0[4] = {0.f,0.f,0.f,0.f}, c0[4] = {0.f,0.f,0.f,0.f};
            float a1[4] = {0.f,0.f,0.f,0.f}, b1[4] = {0.f,0.f,0.f,0.f}, c1[4] = {0.f,0.f,0.f,0.f};
            #pragma unroll
            for (int kk = 0; kk < 8; kk++) {
                u32 chunk = (u32)(((kk << 1) + hi8) ^ swA);
                u32 ah[4], al[4];
                ldsm_x4(ah, aRowH + (chunk << 4));
                ldsm_x4(al, aRowL + (chunk << 4));
                mma16816(a0, ah, ubh[kk][0]);
                mma16816(b0, al, ubh[kk][0]);
                mma16816(c0, ah, ubl[kk][0]);
                mma16816(a1, ah, ubh[kk][1]);
                mma16816(b1, al, ubh[kk][1]);
                mma16816(c1, ah, ubl[kk][1]);
            }
            *(float2*)&sm.spart[warp][r][cc2] =
                make_float2(a0[0] + b0[0] + c0[0], a0[1] + b0[1] + c0[1]);
            *(float2*)&sm.spart[warp][r + 8][cc2] =
                make_float2(a0[2] + b0[2] + c0[2], a0[3] + b0[3] + c0[3]);
            *(float2*)&sm.spart[warp][r][8 + cc2] =
                make_float2(a1[0] + b1[0] + c1[0], a1[1] + b1[1] + c1[1]);
            *(float2*)&sm.spart[warp][r + 8][8 + cc2] =
                make_float2(a1[2] + b1[2] + c1[2], a1[3] + b1[3] + c1[3]);
        }
        __syncthreads();   // (C) spart complete across warps

        // ---- combine partials + online softmax (warp w: heads 2w, 2w+1) ----
        {
            int hh = 2 * warp + (lane >> 4);
            int t = lane & 15;
            int vtok = len - k * SUB; if (vtok > SUB) vtok = SUB;
            float s = 0.f;
            #pragma unroll
            for (int w = 0; w < 8; w++) s += sm.spart[w][t][hh];
            float mloc = (t < vtok) ? s : -1e30f;
            #pragma unroll
            for (int o = 1; o < 16; o <<= 1)
                mloc = fmaxf(mloc, __shfl_xor_sync(0xffffffffu, mloc, o));
            float mold = sm.mrun[hh];
            float mnew = fmaxf(mold, mloc);
            float wgt = (t < vtok) ? __expf(s - mnew) : 0.f;
            sm.wts[hh][t] = wgt;
            float ssum = wgt;
            #pragma unroll
            for (int o = 1; o < 16; o <<= 1)
                ssum += __shfl_xor_sync(0xffffffffu, ssum, o);
            if (t == 0) {
                float rr = __expf(mold - mnew);
                sm.rfac[hh] = rr;
                sm.mrun[hh] = mnew;
                sm.srun[hh] = sm.srun[hh] * rr + ssum;
                if (rr != 1.0f) sm.norescale = 0;
            }
        }
        __syncthreads();   // (D) weights + flag ready

        // ---- z via tensor cores: Z[16h x 128c] += W[16h x 16t] . X[16t x 128c]
        {
            u32 wah[4], wal[4];
            split2(sm.wts[r][cc2],     sm.wts[r][cc2 + 1],     wah[0], wal[0]);
            split2(sm.wts[r + 8][cc2], sm.wts[r + 8][cc2 + 1], wah[1], wal[1]);
            split2(sm.wts[r][cc2 + 8],     sm.wts[r][cc2 + 9],     wah[2], wal[2]);
            split2(sm.wts[r + 8][cc2 + 8], sm.wts[r + 8][cc2 + 9], wah[3], wal[3]);

            if (!sm.norescale) {          // block-uniform branch; exact skip
                float rf0 = sm.rfac[r], rf1 = sm.rfac[r + 8];
                #pragma unroll
                for (int nt = 0; nt < 16; nt++) {
                    zd[nt][0] *= rf0; zd[nt][1] *= rf0;
                    zd[nt][2] *= rf1; zd[nt][3] *= rf1;
                }
            }

            #pragma unroll
            for (int nt = 0; nt < 16; nt++) {
                u32 chunk = (u32)(nt ^ swB);
                u32 bh[2], bl[2];
                ldsm_x2t(bh, bRowH + (chunk << 4));
                ldsm_x2t(bl, bRowL + (chunk << 4));
                float* d = zd[nt];
                mma16816(d, wah, bh);   // Whi * Xhi
                mma16816(d, wal, bh);   // Wlo * Xhi
                mma16816(d, wah, bl);   // Whi * Xlo
            }
        }
        // next iteration's top __syncwarp orders z reads vs bf16 overwrite
    }

    // ---- epilogue: write chunk state + partial z (D rows = heads) ----
    if (tid < H) {
        g_state[blk][tid] = sm.mrun[tid];
        g_state[blk][H + tid] = sm.srun[tid];
    }
    #pragma unroll
    for (int nt = 0; nt < 16; nt++) {
        int col = warp * 128 + nt * 8 + cc2;
        *(float2*)&g_zp[blk][r][col]     = make_float2(zd[nt][0], zd[nt][1]);
        *(float2*)&g_zp[blk][r + 8][col] = make_float2(zd[nt][2], zd[nt][3]);
    }
}

// ---------------------------------------------------------------------------
// K3: combine chunk partials -> normalized z[b,h,:]
// Grid = B*H*8 CTAs x 128 threads: 32-float4 column segment per CTA,
// 4 strips x 10 chunks per thread (MLP 10), smem cross-strip reduce.
// ---------------------------------------------------------------------------
__global__ void combine_kernel() {
    int bh = blockIdx.x >> 3;
    int seg = blockIdx.x & 7;
    int b = bh >> 4, h = bh & 15;
    __shared__ float4 part[128];
    int tid = threadIdx.x;
    int lane = tid & 31;

    int col = seg * 32 + (tid & 31);     // float4 column 0..255
    int strip = tid >> 5;                // 0..3, 10 chunks each (padded to 40)
    int cbase = strip * 10;

    // issue the 10 independent partial-z loads immediately
    float4 v[10];
    #pragma unroll
    for (int i = 0; i < 10; i++) {
        int cc = cbase + i;
        v[i] = (cc < NC) ? ((const float4*)g_zp[b * NC + cc][h])[col]
                         : make_float4(0.f, 0.f, 0.f, 0.f);
    }

    // redundant per-warp softmax-factor computation (overlaps load latency)
    float m0 = g_state[b * NC + lane][h];
    float m1 = (lane + 32 < NC) ? g_state[b * NC + lane + 32][h] : -1e30f;
    float s0 = g_state[b * NC + lane][H + h];
    float s1 = (lane + 32 < NC) ? g_state[b * NC + lane + 32][H + h] : 0.f;
    float mg = fmaxf(m0, m1);
    #pragma unroll
    for (int o = 16; o; o >>= 1)
        mg = fmaxf(mg, __shfl_xor_sync(0xffffffffu, mg, o));
    float f0 = __expf(m0 - mg), f1 = __expf(m1 - mg);
    float S = f0 * s0 + f1 * s1;
    #pragma unroll
    for (int o = 16; o; o >>= 1)
        S += __shfl_xor_sync(0xffffffffu, S, o);
    float inv = 1.f / S;

    // weighted accumulate; f broadcast via shfl from owning lane
    float4 acc = make_float4(0.f, 0.f, 0.f, 0.f);
    #pragma unroll
    for (int i = 0; i < 10; i++) {
        int cc = cbase + i;
        float flo = __shfl_sync(0xffffffffu, f0, cc & 31);
        float fhi = __shfl_sync(0xffffffffu, f1, (cc - 32) & 31);
        float fv = (cc < 32) ? flo : fhi;
        acc.x += fv * v[i].x; acc.y += fv * v[i].y;
        acc.z += fv * v[i].z; acc.w += fv * v[i].w;
    }
    part[tid] = acc;
    __syncthreads();
    if (strip == 0) {
        float4 z = part[tid];
        #pragma unroll
        for (int s = 1; s < 4; s++) {
            float4 p = part[tid + 32 * s];
            z.x += p.x; z.y += p.y; z.z += p.z; z.w += p.w;
        }
        ((float4*)(g_z + (size_t)(b * H + h) * C))[col] =
            make_float4(z.x * inv, z.y * inv, z.z * inv, z.w * inv);
    }
}

// ---------------------------------------------------------------------------
// K4: y[b,a] = Wv[a,:] . z[b, a/64, :] + bv[a]   (warp per (b,a); grid 512)
// 4 independent accumulator chains (one per float4 component).
// ---------------------------------------------------------------------------
__global__ void y_kernel(const float* __restrict__ Wv,
                         const float* __restrict__ bv,
                         float* __restrict__ out) {
    int gw = blockIdx.x * 8 + (threadIdx.x >> 5);
    int lane = threadIdx.x & 31;
    int b = gw >> 10, a = gw & 1023;
    int h = a >> 6;
    const float4* wr = (const float4*)(Wv + (size_t)a * C);
    const float4* zr = (const float4*)(g_z + (size_t)(b * H + h) * C);
    float s0 = 0.f, s1 = 0.f, s2 = 0.f, s3 = 0.f;
    #pragma unroll 8
    for (int c = lane; c < C / 4; c += 32) {
        float4 w = wr[c], zv = zr[c];
        s0 += w.x * zv.x;
        s1 += w.y * zv.y;
        s2 += w.z * zv.z;
        s3 += w.w * zv.w;
    }
    float s = (s0 + s1) + (s2 + s3);
    #pragma unroll
    for (int o = 16; o; o >>= 1) s += __shfl_down_sync(0xffffffffu, s, o);
    if (!lane) out[b * A + a] = s + bv[a];
}

// ---------------------------------------------------------------------------
extern "C" void kernel_launch(void* const* d_in, const int* in_sizes, int n_in,
                              void* d_out, int out_size) {
    const float* x  = (const float*)d_in[0];
    const float* Wk = (const float*)d_in[1];
    // d_in[2] = bk: per-(b,h) constant, cancels in softmax
    const float* Wq = (const float*)d_in[3];
    const float* bq = (const float*)d_in[4];
    const float* Wv = (const float*)d_in[5];
    const float* bv = (const float*)d_in[6];
    float* out = (float*)d_out;

    cudaFuncSetAttribute(fused_kernel,
                         cudaFuncAttributeMaxDynamicSharedMemorySize,
                         (int)sizeof(FSmem));

    q_kernel<<<(B * A) / 8, 256>>>(x, Wq, bq);
    u_kernel<<<H * 8, 128>>>(Wk);
    fused_kernel<<<GRID, 256, sizeof(FSmem)>>>(x);
    combine_kernel<<<B * H * 8, 128>>>();
    y_kernel<<<(B * A) / 8, 256>>>(Wv, bv, out);
}